// round 5
// baseline (speedup 1.0000x reference)
#include <cuda_runtime.h>
#include <cuda_bf16.h>
#include <cstdint>

// ============================================================================
// Problem constants
// ============================================================================
#define NB     16384           // batches
#define NNODE  12              // nodes per batch
#define CDIM   512             // channels
#define ROWS   (NB * NNODE)    // 196608 flat rows
#define KDIM   1024            // GEMM K  ( [y | x] )
#define NDIM   512             // GEMM N  (output channels)
#define TOPK   4
#define BN_EPS 1e-5f

// ============================================================================
// Helpers (baseline PTX only — no sm_103a-accelerated features)
// ============================================================================
__device__ __forceinline__ uint32_t smem_u32(const void* p) {
    uint32_t a;
    asm("{ .reg .u64 t; cvta.to.shared.u64 t, %1; cvt.u32.u64 %0, t; }" : "=r"(a) : "l"(p));
    return a;
}
__device__ __forceinline__ uint32_t lds32(uint32_t addr) {
    uint32_t v;
    asm volatile("ld.shared.b32 %0, [%1];" : "=r"(v) : "r"(addr));
    return v;
}
// D += A * B^T : m16n8k16 row.col bf16 -> f32
__device__ __forceinline__ void mma_bf16(float* d, const uint32_t* a, const uint32_t* b) {
    asm volatile(
        "mma.sync.aligned.m16n8k16.row.col.f32.bf16.bf16.f32 "
        "{%0,%1,%2,%3}, {%4,%5,%6,%7}, {%8,%9}, {%0,%1,%2,%3};"
        : "+f"(d[0]), "+f"(d[1]), "+f"(d[2]), "+f"(d[3])
        : "r"(a[0]), "r"(a[1]), "r"(a[2]), "r"(a[3]), "r"(b[0]), "r"(b[1]));
}
// pack two floats' bf16-hi parts into one u32 (lo bits = first elem)
__device__ __forceinline__ uint32_t pack_hi2(float a, float b) {
    __nv_bfloat162 t;
    t.x = __float2bfloat16(a);
    t.y = __float2bfloat16(b);
    return *reinterpret_cast<uint32_t*>(&t);
}
__device__ __forceinline__ uint32_t pack_lo2(float a, float b) {
    __nv_bfloat162 t;
    __nv_bfloat16 ha = __float2bfloat16(a);
    __nv_bfloat16 hb = __float2bfloat16(b);
    t.x = __float2bfloat16(a - __bfloat162float(ha));
    t.y = __float2bfloat16(b - __bfloat162float(hb));
    return *reinterpret_cast<uint32_t*>(&t);
}

// ============================================================================
// Device scratch
// ============================================================================
__device__ __align__(16) __nv_bfloat16 g_yhi[(size_t)ROWS * CDIM];
__device__ __align__(16) __nv_bfloat16 g_ylo[(size_t)ROWS * CDIM];
__device__ __align__(16) __nv_bfloat16 g_whi[(size_t)NDIM * KDIM];
__device__ __align__(16) __nv_bfloat16 g_wlo[(size_t)NDIM * KDIM];
__device__ __align__(16) float g_h[(size_t)ROWS * CDIM];
__device__ float g_rs[ROWS];
__device__ float g_sum[NNODE];
__device__ float g_sumsq[NNODE];
__device__ float g_scale[NNODE];
__device__ float g_shift[NNODE];

// ============================================================================
// Kernel 0a: zero the stat accumulators
// ============================================================================
__global__ void k_zero_stats() {
    int t = threadIdx.x;
    if (t < NNODE) { g_sum[t] = 0.f; g_sumsq[t] = 0.f; }
}

// ============================================================================
// Kernel 0b: pack W = [Vw | Uw] as bf16 hi/lo  (Wcat[d,k], K-major)
// ============================================================================
__global__ void k_prep_w(const float* __restrict__ Uw, const float* __restrict__ Vw) {
    int idx = blockIdx.x * blockDim.x + threadIdx.x;
    if (idx >= NDIM * KDIM) return;
    int d = idx >> 10;
    int k = idx & 1023;
    float v = (k < 512) ? Vw[d * 512 + k] : Uw[d * 512 + (k - 512)];
    __nv_bfloat16 hi = __float2bfloat16(v);
    float lo = v - __bfloat162float(hi);
    g_whi[idx] = hi;
    g_wlo[idx] = __float2bfloat16(lo);
}

// ============================================================================
// Kernel 1: per-batch adjacency + aggregation   y = A @ x,  rs = rowsum(A)
// ============================================================================
__global__ __launch_bounds__(128) void k_adjacency(const float* __restrict__ x) {
    __shared__ __align__(16) float sx[NNODE][CDIM];
    __shared__ float ssim[NNODE][NNODE];
    __shared__ float sA[NNODE][NNODE];
    __shared__ float sthr[NNODE];
    __shared__ float sdinv[NNODE];

    const int tid = threadIdx.x;
    const int b   = blockIdx.x;

    {
        const float4* src = reinterpret_cast<const float4*>(x + (size_t)b * NNODE * CDIM);
        float4* dst = reinterpret_cast<float4*>(&sx[0][0]);
        for (int i = tid; i < NNODE * CDIM / 4; i += 128) dst[i] = src[i];
    }
    __syncthreads();

    if (tid < 78) {
        int i = 0, t = tid;
        while (t >= NNODE - i) { t -= NNODE - i; i++; }
        int j = i + t;
        float acc = 0.f;
        #pragma unroll 4
        for (int c = 0; c < CDIM; c += 4) {
            float4 a  = *reinterpret_cast<const float4*>(&sx[i][c]);
            float4 bb = *reinterpret_cast<const float4*>(&sx[j][c]);
            acc += a.x * bb.x + a.y * bb.y + a.z * bb.z + a.w * bb.w;
        }
        ssim[i][j] = acc;
        ssim[j][i] = acc;
    }
    __syncthreads();

    if (tid < NNODE) {
        float v[NNODE];
        #pragma unroll
        for (int j = 0; j < NNODE; j++) v[j] = ssim[tid][j];
        float thr = 0.f;
        #pragma unroll
        for (int t = 0; t < TOPK; t++) {
            int m = 0;
            float mv = v[0];
            #pragma unroll
            for (int j = 1; j < NNODE; j++) if (v[j] > mv) { mv = v[j]; m = j; }
            thr = mv;
            v[m] = -3.4e38f;
        }
        sthr[tid] = thr;
        int deg = 0;
        #pragma unroll
        for (int j = 0; j < NNODE; j++) deg += (ssim[tid][j] >= thr) ? 1 : 0;
        sdinv[tid] = rsqrtf((float)deg);
    }
    __syncthreads();

    // FIX (R5): 144 entries > 128 threads — grid-stride so sA[10][8..] and
    // sA[11][*] are actually written (previously uninitialized smem!)
    for (int t = tid; t < NNODE * NNODE; t += 128) {
        int i = t / NNODE, j = t % NNODE;
        float adj = (ssim[i][j] >= sthr[i]) ? 1.f : 0.f;
        sA[i][j] = sdinv[i] * sdinv[j] * adj;
    }
    __syncthreads();

    if (tid < NNODE) {
        float rs = 0.f;
        #pragma unroll
        for (int j = 0; j < NNODE; j++) rs += sA[tid][j];
        g_rs[(size_t)b * NNODE + tid] = rs;
    }

    for (int i = 0; i < NNODE; i++) {
        float ar[NNODE];
        #pragma unroll
        for (int j = 0; j < NNODE; j++) ar[j] = sA[i][j];
        for (int c = tid; c < CDIM; c += 128) {
            float acc = 0.f;
            #pragma unroll
            for (int j = 0; j < NNODE; j++) acc += ar[j] * sx[j][c];
            __nv_bfloat16 hi = __float2bfloat16(acc);
            float lo = acc - __bfloat162float(hi);
            size_t o = ((size_t)b * NNODE + i) * CDIM + c;
            g_yhi[o] = hi;
            g_ylo[o] = __float2bfloat16(lo);
        }
    }
}

// ============================================================================
// Kernel 2: GEMM  h = [y|x] @ Wcat^T + rs*Vb + Ub   (bf16x3 split, HMMA)
// BM=128, BN=128, BK=32, 256 threads, double-buffered smem.
// ============================================================================
#define LDA        40                      // padded row (bf16 elems): 80 bytes
#define TILE_B     (128 * LDA)             // one operand region (bf16 elems)
#define STAGE_E    (4 * TILE_B)            // A_hi, A_lo, B_hi, B_lo
#define SMEM2_BYTES (2 * STAGE_E * 2)      // 81920 bytes

__global__ __launch_bounds__(256, 1) void k_gemm(const float* __restrict__ x,
                                                 const float* __restrict__ Vb,
                                                 const float* __restrict__ Ub) {
    extern __shared__ __align__(128) __nv_bfloat16 sm[];
    __shared__ float sBias[256];

    const int tid  = threadIdx.x;
    const int wid  = tid >> 5;
    const int lane = tid & 31;

    const int ntile = blockIdx.x & 3;
    const int mtile = blockIdx.x >> 2;
    const int mrow0 = mtile * 128;
    const int n0    = ntile * 128;

    const int wm = (wid & 3) * 32;     // warp m offset
    const int wn = (wid >> 2) * 64;    // warp n offset

    for (int i = tid; i < 128; i += 256) {
        sBias[i]       = Vb[n0 + i];
        sBias[128 + i] = Ub[n0 + i];
    }

    float acc[2][8][4];
    #pragma unroll
    for (int mi = 0; mi < 2; mi++)
        #pragma unroll
        for (int nb = 0; nb < 8; nb++)
            #pragma unroll
            for (int q = 0; q < 4; q++) acc[mi][nb][q] = 0.f;

    const int arow = tid >> 1;          // 0..127
    const int acol = (tid & 1) * 16;    // 0 / 16
    const uint32_t sm_addr = smem_u32(sm);

    uint4 ra[4], rb[4];

    // ---- load + stage first chunk (kc=0: A from y hi/lo) ----
    {
        size_t ga = (size_t)(mrow0 + arow) * CDIM + acol;
        ra[0] = *reinterpret_cast<const uint4*>(g_yhi + ga);
        ra[1] = *reinterpret_cast<const uint4*>(g_yhi + ga + 8);
        ra[2] = *reinterpret_cast<const uint4*>(g_ylo + ga);
        ra[3] = *reinterpret_cast<const uint4*>(g_ylo + ga + 8);
        size_t gw = (size_t)(n0 + arow) * KDIM + acol;
        rb[0] = *reinterpret_cast<const uint4*>(g_whi + gw);
        rb[1] = *reinterpret_cast<const uint4*>(g_whi + gw + 8);
        rb[2] = *reinterpret_cast<const uint4*>(g_wlo + gw);
        rb[3] = *reinterpret_cast<const uint4*>(g_wlo + gw + 8);

        __nv_bfloat16* s = sm;
        int off = arow * LDA + acol;
        *reinterpret_cast<uint4*>(s + off)                = ra[0];
        *reinterpret_cast<uint4*>(s + off + 8)            = ra[1];
        *reinterpret_cast<uint4*>(s + TILE_B + off)       = ra[2];
        *reinterpret_cast<uint4*>(s + TILE_B + off + 8)   = ra[3];
        *reinterpret_cast<uint4*>(s + 2*TILE_B + off)     = rb[0];
        *reinterpret_cast<uint4*>(s + 2*TILE_B + off + 8) = rb[1];
        *reinterpret_cast<uint4*>(s + 3*TILE_B + off)     = rb[2];
        *reinterpret_cast<uint4*>(s + 3*TILE_B + off + 8) = rb[3];
    }
    __syncthreads();

    const int frow  = lane >> 2;        // t/4
    const int fkp   = (lane & 3) * 2;   // 2*(t%4)

    #pragma unroll 1
    for (int kc = 0; kc < 32; kc++) {
        // ---- prefetch next chunk into registers ----
        const int kn = kc + 1;
        if (kn < 32) {
            if (kn < 16) {
                size_t ga = (size_t)(mrow0 + arow) * CDIM + kn * 32 + acol;
                ra[0] = *reinterpret_cast<const uint4*>(g_yhi + ga);
                ra[1] = *reinterpret_cast<const uint4*>(g_yhi + ga + 8);
                ra[2] = *reinterpret_cast<const uint4*>(g_ylo + ga);
                ra[3] = *reinterpret_cast<const uint4*>(g_ylo + ga + 8);
            } else {
                size_t ga = (size_t)(mrow0 + arow) * CDIM + (kn - 16) * 32 + acol;
                const float4* xs = reinterpret_cast<const float4*>(x + ga);
                ra[0] = *reinterpret_cast<const uint4*>(xs + 0);
                ra[1] = *reinterpret_cast<const uint4*>(xs + 1);
                ra[2] = *reinterpret_cast<const uint4*>(xs + 2);
                ra[3] = *reinterpret_cast<const uint4*>(xs + 3);
            }
            size_t gw = (size_t)(n0 + arow) * KDIM + kn * 32 + acol;
            rb[0] = *reinterpret_cast<const uint4*>(g_whi + gw);
            rb[1] = *reinterpret_cast<const uint4*>(g_whi + gw + 8);
            rb[2] = *reinterpret_cast<const uint4*>(g_wlo + gw);
            rb[3] = *reinterpret_cast<const uint4*>(g_wlo + gw + 8);
        }

        // ---- compute on stage kc&1 (manual LDS fragments) ----
        {
            const uint32_t sA_hi = sm_addr + (uint32_t)(kc & 1) * (STAGE_E * 2);
            const uint32_t sA_lo = sA_hi + TILE_B * 2;
            const uint32_t sB_hi = sA_hi + 2 * TILE_B * 2;
            const uint32_t sB_lo = sA_hi + 3 * TILE_B * 2;

            #pragma unroll
            for (int ks = 0; ks < 2; ks++) {
                const int k0 = ks * 16;
                uint32_t aH[2][4], aL[2][4];
                #pragma unroll
                for (int mi = 0; mi < 2; mi++) {
                    const int r0 = wm + mi * 16 + frow;
                    uint32_t o00 = (uint32_t)(r0 * LDA + k0 + fkp) * 2;
                    uint32_t o10 = (uint32_t)((r0 + 8) * LDA + k0 + fkp) * 2;
                    aH[mi][0] = lds32(sA_hi + o00);
                    aH[mi][1] = lds32(sA_hi + o10);
                    aH[mi][2] = lds32(sA_hi + o00 + 16);   // k+8 -> +16 bytes
                    aH[mi][3] = lds32(sA_hi + o10 + 16);
                    aL[mi][0] = lds32(sA_lo + o00);
                    aL[mi][1] = lds32(sA_lo + o10);
                    aL[mi][2] = lds32(sA_lo + o00 + 16);
                    aL[mi][3] = lds32(sA_lo + o10 + 16);
                }
                #pragma unroll
                for (int nb = 0; nb < 8; nb++) {
                    const int bn = wn + nb * 8 + frow;     // n = t/4
                    uint32_t ob = (uint32_t)(bn * LDA + k0 + fkp) * 2;
                    uint32_t bH[2], bL[2];
                    bH[0] = lds32(sB_hi + ob);
                    bH[1] = lds32(sB_hi + ob + 16);
                    bL[0] = lds32(sB_lo + ob);
                    bL[1] = lds32(sB_lo + ob + 16);
                    #pragma unroll
                    for (int mi = 0; mi < 2; mi++) {
                        mma_bf16(acc[mi][nb], aH[mi], bH);
                        mma_bf16(acc[mi][nb], aL[mi], bH);
                        mma_bf16(acc[mi][nb], aH[mi], bL);
                    }
                }
            }
        }
        __syncthreads();

        // ---- stage the prefetched chunk ----
        if (kn < 32) {
            __nv_bfloat16* s = sm + (kn & 1) * STAGE_E;
            int off = arow * LDA + acol;
            if (kn < 16) {
                *reinterpret_cast<uint4*>(s + off)              = ra[0];
                *reinterpret_cast<uint4*>(s + off + 8)          = ra[1];
                *reinterpret_cast<uint4*>(s + TILE_B + off)     = ra[2];
                *reinterpret_cast<uint4*>(s + TILE_B + off + 8) = ra[3];
            } else {
                const float4* f4 = reinterpret_cast<const float4*>(ra);
                uint4 hiA, hiB, loA, loB;
                float4 v0 = f4[0], v1 = f4[1], v2 = f4[2], v3 = f4[3];
                hiA.x = pack_hi2(v0.x, v0.y); hiA.y = pack_hi2(v0.z, v0.w);
                hiA.z = pack_hi2(v1.x, v1.y); hiA.w = pack_hi2(v1.z, v1.w);
                hiB.x = pack_hi2(v2.x, v2.y); hiB.y = pack_hi2(v2.z, v2.w);
                hiB.z = pack_hi2(v3.x, v3.y); hiB.w = pack_hi2(v3.z, v3.w);
                loA.x = pack_lo2(v0.x, v0.y); loA.y = pack_lo2(v0.z, v0.w);
                loA.z = pack_lo2(v1.x, v1.y); loA.w = pack_lo2(v1.z, v1.w);
                loB.x = pack_lo2(v2.x, v2.y); loB.y = pack_lo2(v2.z, v2.w);
                loB.z = pack_lo2(v3.x, v3.y); loB.w = pack_lo2(v3.z, v3.w);
                *reinterpret_cast<uint4*>(s + off)              = hiA;
                *reinterpret_cast<uint4*>(s + off + 8)          = hiB;
                *reinterpret_cast<uint4*>(s + TILE_B + off)     = loA;
                *reinterpret_cast<uint4*>(s + TILE_B + off + 8) = loB;
            }
            *reinterpret_cast<uint4*>(s + 2*TILE_B + off)     = rb[0];
            *reinterpret_cast<uint4*>(s + 2*TILE_B + off + 8) = rb[1];
            *reinterpret_cast<uint4*>(s + 3*TILE_B + off)     = rb[2];
            *reinterpret_cast<uint4*>(s + 3*TILE_B + off + 8) = rb[3];
            __syncthreads();
        }
    }

    // ---- epilogue: bias + write h (stats handled by k_stats) ----
    const int l4 = lane >> 2;
    const int lc = (lane & 3) * 2;

    #pragma unroll
    for (int mi = 0; mi < 2; mi++) {
        #pragma unroll
        for (int rr = 0; rr < 2; rr++) {
            const int row = wm + mi * 16 + rr * 8 + l4;
            const size_t grow = (size_t)mrow0 + row;
            const float rsv = g_rs[grow];
            float* hrow = g_h + grow * CDIM + n0;
            #pragma unroll
            for (int nb = 0; nb < 8; nb++) {
                const int c = wn + nb * 8 + lc;
                float v0 = acc[mi][nb][rr * 2 + 0] + rsv * sBias[c]     + sBias[128 + c];
                float v1 = acc[mi][nb][rr * 2 + 1] + rsv * sBias[c + 1] + sBias[128 + c + 1];
                *reinterpret_cast<float2*>(hrow + c) = make_float2(v0, v1);
            }
        }
    }
}

// ============================================================================
// Kernel 2b: BN statistics from g_h  (warp-per-row, shfl reduce)
// ============================================================================
__global__ __launch_bounds__(256) void k_stats() {
    __shared__ float ss[24];
    const int tid  = threadIdx.x;
    const int wid  = tid >> 5;
    const int lane = tid & 31;

    if (tid < 24) ss[tid] = 0.f;
    __syncthreads();

    const int row0 = blockIdx.x * 128 + wid * 16;
    for (int rr = 0; rr < 16; rr++) {
        const int grow = row0 + rr;
        const float4* hp = reinterpret_cast<const float4*>(g_h + (size_t)grow * CDIM);
        float s = 0.f, q = 0.f;
        #pragma unroll
        for (int u = 0; u < 4; u++) {
            float4 v = hp[lane + u * 32];
            s += v.x + v.y + v.z + v.w;
            q += v.x * v.x + v.y * v.y + v.z * v.z + v.w * v.w;
        }
        #pragma unroll
        for (int o = 16; o > 0; o >>= 1) {
            s += __shfl_xor_sync(0xFFFFFFFF, s, o);
            q += __shfl_xor_sync(0xFFFFFFFF, q, o);
        }
        if (lane == 0) {
            int node = grow % NNODE;
            atomicAdd(&ss[node], s);
            atomicAdd(&ss[12 + node], q);
        }
    }
    __syncthreads();
    if (tid < NNODE) {
        atomicAdd(&g_sum[tid], ss[tid]);
        atomicAdd(&g_sumsq[tid], ss[12 + tid]);
    }
}

// ============================================================================
// Kernel 3: finalize BN stats -> scale/shift per node
// ============================================================================
__global__ void k_finalize(const float* __restrict__ gamma, const float* __restrict__ beta) {
    int t = threadIdx.x;
    if (t < NNODE) {
        const float inv_n = 1.0f / ((float)NB * (float)CDIM);
        float mean = g_sum[t] * inv_n;
        float var  = g_sumsq[t] * inv_n - mean * mean;
        var = fmaxf(var, 0.f);
        float sc = gamma[t] * rsqrtf(var + BN_EPS);
        g_scale[t] = sc;
        g_shift[t] = beta[t] - mean * sc;
    }
}

// ============================================================================
// Kernel 4: out = relu(x + h*scale + shift)
// ============================================================================
__global__ __launch_bounds__(512) void k_output(const float* __restrict__ x,
                                                float* __restrict__ out) {
    size_t idx = (size_t)blockIdx.x * 512 + threadIdx.x;
    const float4 xv = reinterpret_cast<const float4*>(x)[idx];
    const float4 hv = reinterpret_cast<const float4*>(g_h)[idx];
    int node = (int)((idx >> 7) % NNODE);
    float sc = g_scale[node], sh = g_shift[node];
    float4 o;
    o.x = fmaxf(fmaf(hv.x, sc, sh) + xv.x, 0.f);
    o.y = fmaxf(fmaf(hv.y, sc, sh) + xv.y, 0.f);
    o.z = fmaxf(fmaf(hv.z, sc, sh) + xv.z, 0.f);
    o.w = fmaxf(fmaf(hv.w, sc, sh) + xv.w, 0.f);
    reinterpret_cast<float4*>(out)[idx] = o;
}

// ============================================================================
// Launch
// ============================================================================
extern "C" void kernel_launch(void* const* d_in, const int* in_sizes, int n_in,
                              void* d_out, int out_size) {
    const float* x     = (const float*)d_in[0];
    const float* Uw    = (const float*)d_in[1];
    const float* Ub    = (const float*)d_in[2];
    const float* Vw    = (const float*)d_in[3];
    const float* Vb    = (const float*)d_in[4];
    const float* gamma = (const float*)d_in[5];
    const float* beta  = (const float*)d_in[6];
    float* out = (float*)d_out;

    cudaFuncSetAttribute(k_gemm, cudaFuncAttributeMaxDynamicSharedMemorySize, SMEM2_BYTES);

    k_zero_stats<<<1, 32>>>();
    k_prep_w<<<(NDIM * KDIM + 255) / 256, 256>>>(Uw, Vw);
    k_adjacency<<<NB, 128>>>(x);
    k_gemm<<<(ROWS / 128) * 4, 256, SMEM2_BYTES>>>(x, Vb, Ub);
    k_stats<<<ROWS / 128, 256>>>();
    k_finalize<<<1, 32>>>(gamma, beta);
    k_output<<<(unsigned)((size_t)ROWS * CDIM / 4 / 512), 512>>>(x, out);
}

// round 6
// speedup vs baseline: 1.1822x; 1.1822x over previous
#include <cuda_runtime.h>
#include <cuda_bf16.h>
#include <cstdint>

// ============================================================================
// Problem constants
// ============================================================================
#define NB     16384           // batches
#define NNODE  12              // nodes per batch
#define CDIM   512             // channels
#define ROWS   (NB * NNODE)    // 196608 flat rows
#define KDIM   1024            // GEMM K  ( [y | x] )
#define NDIM   512             // GEMM N  (output channels)
#define TOPK   4
#define BN_EPS 1e-5f

// ============================================================================
// Helpers (baseline PTX only)
// ============================================================================
__device__ __forceinline__ uint32_t smem_u32(const void* p) {
    uint32_t a;
    asm("{ .reg .u64 t; cvta.to.shared.u64 t, %1; cvt.u32.u64 %0, t; }" : "=r"(a) : "l"(p));
    return a;
}
__device__ __forceinline__ uint32_t lds32(uint32_t addr) {
    uint32_t v;
    asm volatile("ld.shared.b32 %0, [%1];" : "=r"(v) : "r"(addr));
    return v;
}
__device__ __forceinline__ void cp_async16(uint32_t saddr, const void* gaddr) {
    asm volatile("cp.async.cg.shared.global [%0], [%1], 16;" :: "r"(saddr), "l"(gaddr));
}
#define CP_COMMIT() asm volatile("cp.async.commit_group;" ::: "memory")
#define CP_WAIT1()  asm volatile("cp.async.wait_group 1;" ::: "memory")

// D += A * B^T : m16n8k16 row.col bf16 -> f32
__device__ __forceinline__ void mma_bf16(float* d, const uint32_t* a, const uint32_t* b) {
    asm volatile(
        "mma.sync.aligned.m16n8k16.row.col.f32.bf16.bf16.f32 "
        "{%0,%1,%2,%3}, {%4,%5,%6,%7}, {%8,%9}, {%0,%1,%2,%3};"
        : "+f"(d[0]), "+f"(d[1]), "+f"(d[2]), "+f"(d[3])
        : "r"(a[0]), "r"(a[1]), "r"(a[2]), "r"(a[3]), "r"(b[0]), "r"(b[1]));
}

// ============================================================================
// Device scratch
// g_ahi/g_alo: unified A = [y | x] per row, bf16 hi/lo split  [ROWS x KDIM]
// ============================================================================
__device__ __align__(16) __nv_bfloat16 g_ahi[(size_t)ROWS * KDIM];
__device__ __align__(16) __nv_bfloat16 g_alo[(size_t)ROWS * KDIM];
__device__ __align__(16) __nv_bfloat16 g_whi[(size_t)NDIM * KDIM];
__device__ __align__(16) __nv_bfloat16 g_wlo[(size_t)NDIM * KDIM];
__device__ __align__(16) float g_h[(size_t)ROWS * CDIM];
__device__ float g_rs[ROWS];
__device__ float g_sum[NNODE];
__device__ float g_sumsq[NNODE];
__device__ float g_scale[NNODE];
__device__ float g_shift[NNODE];

// ============================================================================
// Kernel 0a: zero the stat accumulators
// ============================================================================
__global__ void k_zero_stats() {
    int t = threadIdx.x;
    if (t < NNODE) { g_sum[t] = 0.f; g_sumsq[t] = 0.f; }
}

// ============================================================================
// Kernel 0b: pack W = [Vw | Uw] as bf16 hi/lo  (Wcat[d,k], K-major)
// ============================================================================
__global__ void k_prep_w(const float* __restrict__ Uw, const float* __restrict__ Vw) {
    int idx = blockIdx.x * blockDim.x + threadIdx.x;
    if (idx >= NDIM * KDIM) return;
    int d = idx >> 10;
    int k = idx & 1023;
    float v = (k < 512) ? Vw[d * 512 + k] : Uw[d * 512 + (k - 512)];
    __nv_bfloat16 hi = __float2bfloat16(v);
    float lo = v - __bfloat162float(hi);
    g_whi[idx] = hi;
    g_wlo[idx] = __float2bfloat16(lo);
}

// ============================================================================
// Kernel 1: adjacency + aggregation.  Writes A-operand rows [y | x] (hi/lo).
// ============================================================================
__global__ __launch_bounds__(128) void k_adjacency(const float* __restrict__ x) {
    __shared__ __align__(16) float sx[NNODE][CDIM];
    __shared__ float ssim[NNODE][NNODE];
    __shared__ float sA[NNODE][NNODE];
    __shared__ float sthr[NNODE];
    __shared__ float sdinv[NNODE];

    const int tid = threadIdx.x;
    const int b   = blockIdx.x;

    {
        const float4* src = reinterpret_cast<const float4*>(x + (size_t)b * NNODE * CDIM);
        float4* dst = reinterpret_cast<float4*>(&sx[0][0]);
        for (int i = tid; i < NNODE * CDIM / 4; i += 128) dst[i] = src[i];
    }
    __syncthreads();

    if (tid < 78) {
        int i = 0, t = tid;
        while (t >= NNODE - i) { t -= NNODE - i; i++; }
        int j = i + t;
        float acc = 0.f;
        #pragma unroll 4
        for (int c = 0; c < CDIM; c += 4) {
            float4 a  = *reinterpret_cast<const float4*>(&sx[i][c]);
            float4 bb = *reinterpret_cast<const float4*>(&sx[j][c]);
            acc += a.x * bb.x + a.y * bb.y + a.z * bb.z + a.w * bb.w;
        }
        ssim[i][j] = acc;
        ssim[j][i] = acc;
    }
    __syncthreads();

    if (tid < NNODE) {
        float v[NNODE];
        #pragma unroll
        for (int j = 0; j < NNODE; j++) v[j] = ssim[tid][j];
        float thr = 0.f;
        #pragma unroll
        for (int t = 0; t < TOPK; t++) {
            int m = 0;
            float mv = v[0];
            #pragma unroll
            for (int j = 1; j < NNODE; j++) if (v[j] > mv) { mv = v[j]; m = j; }
            thr = mv;
            v[m] = -3.4e38f;
        }
        sthr[tid] = thr;
        int deg = 0;
        #pragma unroll
        for (int j = 0; j < NNODE; j++) deg += (ssim[tid][j] >= thr) ? 1 : 0;
        sdinv[tid] = rsqrtf((float)deg);
    }
    __syncthreads();

    for (int t = tid; t < NNODE * NNODE; t += 128) {   // 144 > 128: grid-stride
        int i = t / NNODE, j = t % NNODE;
        float adj = (ssim[i][j] >= sthr[i]) ? 1.f : 0.f;
        sA[i][j] = sdinv[i] * sdinv[j] * adj;
    }
    __syncthreads();

    if (tid < NNODE) {
        float rs = 0.f;
        #pragma unroll
        for (int j = 0; j < NNODE; j++) rs += sA[tid][j];
        g_rs[(size_t)b * NNODE + tid] = rs;
    }

    // y = A @ x  -> cols [0,512) of A-operand
    for (int i = 0; i < NNODE; i++) {
        float ar[NNODE];
        #pragma unroll
        for (int j = 0; j < NNODE; j++) ar[j] = sA[i][j];
        for (int c = tid; c < CDIM; c += 128) {
            float acc = 0.f;
            #pragma unroll
            for (int j = 0; j < NNODE; j++) acc += ar[j] * sx[j][c];
            __nv_bfloat16 hi = __float2bfloat16(acc);
            float lo = acc - __bfloat162float(hi);
            size_t o = ((size_t)b * NNODE + i) * KDIM + c;
            g_ahi[o] = hi;
            g_alo[o] = __float2bfloat16(lo);
        }
    }

    // x -> cols [512,1024) of A-operand
    for (int u = tid; u < NNODE * CDIM; u += 128) {
        int i = u >> 9, c = u & 511;
        float v = sx[i][c];
        __nv_bfloat16 hi = __float2bfloat16(v);
        float lo = v - __bfloat162float(hi);
        size_t o = ((size_t)b * NNODE + i) * KDIM + 512 + c;
        g_ahi[o] = hi;
        g_alo[o] = __float2bfloat16(lo);
    }
}

// ============================================================================
// Kernel 2: GEMM  h = [y|x] @ Wcat^T + rs*Vb + Ub   (bf16x3 split, HMMA)
// BM=128, BN=128, BK=32, 256 threads, 2-stage cp.async, 2 CTAs/SM.
// ============================================================================
#define LDA        40                      // padded row (bf16 elems): 80 bytes
#define TILE_B     (128 * LDA)             // one operand region (bf16 elems)
#define STAGE_E    (4 * TILE_B)            // A_hi, A_lo, B_hi, B_lo
#define STAGE_BYTES (STAGE_E * 2)          // 40960
#define SMEM2_BYTES (2 * STAGE_BYTES)      // 81920

__device__ __forceinline__ void issue_chunk(uint32_t sbase, int mrow0, int n0,
                                            int kc, int arow, int acol) {
    const size_t ga = (size_t)(mrow0 + arow) * KDIM + kc * 32 + acol;
    const size_t gw = (size_t)(n0 + arow) * KDIM + kc * 32 + acol;
    const uint32_t off = (uint32_t)(arow * LDA + acol) * 2;
    cp_async16(sbase + off,                     g_ahi + ga);
    cp_async16(sbase + off + 16,                g_ahi + ga + 8);
    cp_async16(sbase + TILE_B * 2 + off,        g_alo + ga);
    cp_async16(sbase + TILE_B * 2 + off + 16,   g_alo + ga + 8);
    cp_async16(sbase + 2 * TILE_B * 2 + off,      g_whi + gw);
    cp_async16(sbase + 2 * TILE_B * 2 + off + 16, g_whi + gw + 8);
    cp_async16(sbase + 3 * TILE_B * 2 + off,      g_wlo + gw);
    cp_async16(sbase + 3 * TILE_B * 2 + off + 16, g_wlo + gw + 8);
}

__global__ __launch_bounds__(256, 2) void k_gemm(const float* __restrict__ Vb,
                                                 const float* __restrict__ Ub) {
    extern __shared__ __align__(128) __nv_bfloat16 sm[];
    __shared__ float sBias[256];

    const int tid  = threadIdx.x;
    const int wid  = tid >> 5;
    const int lane = tid & 31;

    const int ntile = blockIdx.x & 3;
    const int mtile = blockIdx.x >> 2;
    const int mrow0 = mtile * 128;
    const int n0    = ntile * 128;

    const int wm = (wid & 3) * 32;     // warp m offset
    const int wn = (wid >> 2) * 64;    // warp n offset

    for (int i = tid; i < 128; i += 256) {
        sBias[i]       = Vb[n0 + i];
        sBias[128 + i] = Ub[n0 + i];
    }

    float acc[2][8][4];
    #pragma unroll
    for (int mi = 0; mi < 2; mi++)
        #pragma unroll
        for (int nb = 0; nb < 8; nb++)
            #pragma unroll
            for (int q = 0; q < 4; q++) acc[mi][nb][q] = 0.f;

    const int arow = tid >> 1;          // 0..127
    const int acol = (tid & 1) * 16;    // 0 / 16
    const uint32_t sm_addr = smem_u32(sm);

    // ---- prologue: fill both stages ----
    issue_chunk(sm_addr, mrow0, n0, 0, arow, acol);
    CP_COMMIT();
    issue_chunk(sm_addr + STAGE_BYTES, mrow0, n0, 1, arow, acol);
    CP_COMMIT();

    const int frow = lane >> 2;        // t/4
    const int fkp  = (lane & 3) * 2;   // 2*(t%4)

    #pragma unroll 1
    for (int kc = 0; kc < 32; kc++) {
        CP_WAIT1();
        __syncthreads();

        // ---- compute on stage kc&1 ----
        {
            const uint32_t sA_hi = sm_addr + (uint32_t)(kc & 1) * STAGE_BYTES;
            const uint32_t sA_lo = sA_hi + TILE_B * 2;
            const uint32_t sB_hi = sA_hi + 2 * TILE_B * 2;
            const uint32_t sB_lo = sA_hi + 3 * TILE_B * 2;

            #pragma unroll
            for (int ks = 0; ks < 2; ks++) {
                const int k0 = ks * 16;
                uint32_t aH[2][4], aL[2][4];
                #pragma unroll
                for (int mi = 0; mi < 2; mi++) {
                    const int r0 = wm + mi * 16 + frow;
                    uint32_t o00 = (uint32_t)(r0 * LDA + k0 + fkp) * 2;
                    uint32_t o10 = (uint32_t)((r0 + 8) * LDA + k0 + fkp) * 2;
                    aH[mi][0] = lds32(sA_hi + o00);
                    aH[mi][1] = lds32(sA_hi + o10);
                    aH[mi][2] = lds32(sA_hi + o00 + 16);
                    aH[mi][3] = lds32(sA_hi + o10 + 16);
                    aL[mi][0] = lds32(sA_lo + o00);
                    aL[mi][1] = lds32(sA_lo + o10);
                    aL[mi][2] = lds32(sA_lo + o00 + 16);
                    aL[mi][3] = lds32(sA_lo + o10 + 16);
                }
                #pragma unroll
                for (int nb = 0; nb < 8; nb++) {
                    const int bn = wn + nb * 8 + frow;
                    uint32_t ob = (uint32_t)(bn * LDA + k0 + fkp) * 2;
                    uint32_t bH[2], bL[2];
                    bH[0] = lds32(sB_hi + ob);
                    bH[1] = lds32(sB_hi + ob + 16);
                    bL[0] = lds32(sB_lo + ob);
                    bL[1] = lds32(sB_lo + ob + 16);
                    #pragma unroll
                    for (int mi = 0; mi < 2; mi++) {
                        mma_bf16(acc[mi][nb], aH[mi], bH);
                        mma_bf16(acc[mi][nb], aL[mi], bH);
                        mma_bf16(acc[mi][nb], aH[mi], bL);
                    }
                }
            }
        }
        __syncthreads();

        // ---- refill the stage just consumed with chunk kc+2 ----
        const int kn = kc + 2;
        if (kn < 32)
            issue_chunk(sm_addr + (uint32_t)(kc & 1) * STAGE_BYTES, mrow0, n0, kn, arow, acol);
        CP_COMMIT();
    }

    // ---- epilogue: bias + write h ----
    const int l4 = lane >> 2;
    const int lc = (lane & 3) * 2;

    #pragma unroll
    for (int mi = 0; mi < 2; mi++) {
        #pragma unroll
        for (int rr = 0; rr < 2; rr++) {
            const int row = wm + mi * 16 + rr * 8 + l4;
            const size_t grow = (size_t)mrow0 + row;
            const float rsv = g_rs[grow];
            float* hrow = g_h + grow * CDIM + n0;
            #pragma unroll
            for (int nb = 0; nb < 8; nb++) {
                const int c = wn + nb * 8 + lc;
                float v0 = acc[mi][nb][rr * 2 + 0] + rsv * sBias[c]     + sBias[128 + c];
                float v1 = acc[mi][nb][rr * 2 + 1] + rsv * sBias[c + 1] + sBias[128 + c + 1];
                *reinterpret_cast<float2*>(hrow + c) = make_float2(v0, v1);
            }
        }
    }
}

// ============================================================================
// Kernel 2b: BN statistics from g_h  (warp-per-row, shfl reduce)
// ============================================================================
__global__ __launch_bounds__(256) void k_stats() {
    __shared__ float ss[24];
    const int tid  = threadIdx.x;
    const int wid  = tid >> 5;
    const int lane = tid & 31;

    if (tid < 24) ss[tid] = 0.f;
    __syncthreads();

    const int row0 = blockIdx.x * 128 + wid * 16;
    for (int rr = 0; rr < 16; rr++) {
        const int grow = row0 + rr;
        const float4* hp = reinterpret_cast<const float4*>(g_h + (size_t)grow * CDIM);
        float s = 0.f, q = 0.f;
        #pragma unroll
        for (int u = 0; u < 4; u++) {
            float4 v = hp[lane + u * 32];
            s += v.x + v.y + v.z + v.w;
            q += v.x * v.x + v.y * v.y + v.z * v.z + v.w * v.w;
        }
        #pragma unroll
        for (int o = 16; o > 0; o >>= 1) {
            s += __shfl_xor_sync(0xFFFFFFFF, s, o);
            q += __shfl_xor_sync(0xFFFFFFFF, q, o);
        }
        if (lane == 0) {
            int node = grow % NNODE;
            atomicAdd(&ss[node], s);
            atomicAdd(&ss[12 + node], q);
        }
    }
    __syncthreads();
    if (tid < NNODE) {
        atomicAdd(&g_sum[tid], ss[tid]);
        atomicAdd(&g_sumsq[tid], ss[12 + tid]);
    }
}

// ============================================================================
// Kernel 3: finalize BN stats -> scale/shift per node
// ============================================================================
__global__ void k_finalize(const float* __restrict__ gamma, const float* __restrict__ beta) {
    int t = threadIdx.x;
    if (t < NNODE) {
        const float inv_n = 1.0f / ((float)NB * (float)CDIM);
        float mean = g_sum[t] * inv_n;
        float var  = g_sumsq[t] * inv_n - mean * mean;
        var = fmaxf(var, 0.f);
        float sc = gamma[t] * rsqrtf(var + BN_EPS);
        g_scale[t] = sc;
        g_shift[t] = beta[t] - mean * sc;
    }
}

// ============================================================================
// Kernel 4: out = relu(x + h*scale + shift)
// ============================================================================
__global__ __launch_bounds__(512) void k_output(const float* __restrict__ x,
                                                float* __restrict__ out) {
    size_t idx = (size_t)blockIdx.x * 512 + threadIdx.x;
    const float4 xv = reinterpret_cast<const float4*>(x)[idx];
    const float4 hv = reinterpret_cast<const float4*>(g_h)[idx];
    int node = (int)((idx >> 7) % NNODE);
    float sc = g_scale[node], sh = g_shift[node];
    float4 o;
    o.x = fmaxf(fmaf(hv.x, sc, sh) + xv.x, 0.f);
    o.y = fmaxf(fmaf(hv.y, sc, sh) + xv.y, 0.f);
    o.z = fmaxf(fmaf(hv.z, sc, sh) + xv.z, 0.f);
    o.w = fmaxf(fmaf(hv.w, sc, sh) + xv.w, 0.f);
    reinterpret_cast<float4*>(out)[idx] = o;
}

// ============================================================================
// Launch
// ============================================================================
extern "C" void kernel_launch(void* const* d_in, const int* in_sizes, int n_in,
                              void* d_out, int out_size) {
    const float* x     = (const float*)d_in[0];
    const float* Uw    = (const float*)d_in[1];
    const float* Ub    = (const float*)d_in[2];
    const float* Vw    = (const float*)d_in[3];
    const float* Vb    = (const float*)d_in[4];
    const float* gamma = (const float*)d_in[5];
    const float* beta  = (const float*)d_in[6];
    float* out = (float*)d_out;

    cudaFuncSetAttribute(k_gemm, cudaFuncAttributeMaxDynamicSharedMemorySize, SMEM2_BYTES);

    k_zero_stats<<<1, 32>>>();
    k_prep_w<<<(NDIM * KDIM + 255) / 256, 256>>>(Uw, Vw);
    k_adjacency<<<NB, 128>>>(x);
    k_gemm<<<(ROWS / 128) * 4, 256, SMEM2_BYTES>>>(Vb, Ub);
    k_stats<<<ROWS / 128, 256>>>();
    k_finalize<<<1, 32>>>(gamma, beta);
    k_output<<<(unsigned)((size_t)ROWS * CDIM / 4 / 512), 512>>>(x, out);
}

// round 7
// speedup vs baseline: 1.2647x; 1.0698x over previous
#include <cuda_runtime.h>
#include <cuda_bf16.h>
#include <cstdint>

// ============================================================================
// Problem constants
// ============================================================================
#define NB     16384           // batches
#define NNODE  12              // nodes per batch
#define CDIM   512             // channels
#define ROWS   (NB * NNODE)    // 196608 flat rows
#define KDIM   1024            // GEMM K  ( [y | x] )
#define NDIM   512             // GEMM N  (output channels)
#define TOPK   4
#define BN_EPS 1e-5f

// ============================================================================
// Helpers (baseline PTX only)
// ============================================================================
__device__ __forceinline__ uint32_t smem_u32(const void* p) {
    uint32_t a;
    asm("{ .reg .u64 t; cvta.to.shared.u64 t, %1; cvt.u32.u64 %0, t; }" : "=r"(a) : "l"(p));
    return a;
}
__device__ __forceinline__ void ldsm_x4(uint32_t* r, uint32_t addr) {
    asm volatile("ldmatrix.sync.aligned.m8n8.x4.shared.b16 {%0,%1,%2,%3}, [%4];"
                 : "=r"(r[0]), "=r"(r[1]), "=r"(r[2]), "=r"(r[3]) : "r"(addr));
}
__device__ __forceinline__ void ldsm_x2(uint32_t* r, uint32_t addr) {
    asm volatile("ldmatrix.sync.aligned.m8n8.x2.shared.b16 {%0,%1}, [%2];"
                 : "=r"(r[0]), "=r"(r[1]) : "r"(addr));
}
__device__ __forceinline__ void cp_async16(uint32_t saddr, const void* gaddr) {
    asm volatile("cp.async.cg.shared.global [%0], [%1], 16;" :: "r"(saddr), "l"(gaddr));
}
#define CP_COMMIT() asm volatile("cp.async.commit_group;" ::: "memory")
#define CP_WAIT1()  asm volatile("cp.async.wait_group 1;" ::: "memory")

// D += A * B^T : m16n8k16 row.col bf16 -> f32
__device__ __forceinline__ void mma_bf16(float* d, const uint32_t* a, const uint32_t* b) {
    asm volatile(
        "mma.sync.aligned.m16n8k16.row.col.f32.bf16.bf16.f32 "
        "{%0,%1,%2,%3}, {%4,%5,%6,%7}, {%8,%9}, {%0,%1,%2,%3};"
        : "+f"(d[0]), "+f"(d[1]), "+f"(d[2]), "+f"(d[3])
        : "r"(a[0]), "r"(a[1]), "r"(a[2]), "r"(a[3]), "r"(b[0]), "r"(b[1]));
}
__device__ __forceinline__ uint32_t pack_hi2(float a, float b) {
    __nv_bfloat162 t;
    t.x = __float2bfloat16(a);
    t.y = __float2bfloat16(b);
    return *reinterpret_cast<uint32_t*>(&t);
}
__device__ __forceinline__ uint32_t pack_lo2(float a, float b) {
    __nv_bfloat162 t;
    __nv_bfloat16 ha = __float2bfloat16(a);
    __nv_bfloat16 hb = __float2bfloat16(b);
    t.x = __float2bfloat16(a - __bfloat162float(ha));
    t.y = __float2bfloat16(b - __bfloat162float(hb));
    return *reinterpret_cast<uint32_t*>(&t);
}

// ============================================================================
// Device scratch
// ============================================================================
__device__ __align__(16) __nv_bfloat16 g_ahi[(size_t)ROWS * KDIM];
__device__ __align__(16) __nv_bfloat16 g_alo[(size_t)ROWS * KDIM];
__device__ __align__(16) __nv_bfloat16 g_whi[(size_t)NDIM * KDIM];
__device__ __align__(16) __nv_bfloat16 g_wlo[(size_t)NDIM * KDIM];
__device__ __align__(16) float g_h[(size_t)ROWS * CDIM];
__device__ float g_rs[ROWS];
__device__ float g_sum[NNODE];
__device__ float g_sumsq[NNODE];
__device__ float g_scale[NNODE];
__device__ float g_shift[NNODE];

// ============================================================================
// Kernel 0a: zero the stat accumulators
// ============================================================================
__global__ void k_zero_stats() {
    int t = threadIdx.x;
    if (t < NNODE) { g_sum[t] = 0.f; g_sumsq[t] = 0.f; }
}

// ============================================================================
// Kernel 0b: pack W = [Vw | Uw] as bf16 hi/lo
// ============================================================================
__global__ void k_prep_w(const float* __restrict__ Uw, const float* __restrict__ Vw) {
    int idx = blockIdx.x * blockDim.x + threadIdx.x;
    if (idx >= NDIM * KDIM) return;
    int d = idx >> 10;
    int k = idx & 1023;
    float v = (k < 512) ? Vw[d * 512 + k] : Uw[d * 512 + (k - 512)];
    __nv_bfloat16 hi = __float2bfloat16(v);
    float lo = v - __bfloat162float(hi);
    g_whi[idx] = hi;
    g_wlo[idx] = __float2bfloat16(lo);
}

// ============================================================================
// Kernel 1: adjacency + aggregation.  Writes A-operand rows [y | x] (hi/lo).
// ============================================================================
__global__ __launch_bounds__(128) void k_adjacency(const float* __restrict__ x) {
    __shared__ __align__(16) float sx[NNODE][CDIM];
    __shared__ float ssim[NNODE][NNODE];
    __shared__ float sA[NNODE][NNODE];
    __shared__ float sthr[NNODE];
    __shared__ float sdinv[NNODE];

    const int tid = threadIdx.x;
    const int b   = blockIdx.x;

    {
        const float4* src = reinterpret_cast<const float4*>(x + (size_t)b * NNODE * CDIM);
        float4* dst = reinterpret_cast<float4*>(&sx[0][0]);
        for (int i = tid; i < NNODE * CDIM / 4; i += 128) dst[i] = src[i];
    }
    __syncthreads();

    if (tid < 78) {
        int i = 0, t = tid;
        while (t >= NNODE - i) { t -= NNODE - i; i++; }
        int j = i + t;
        float acc = 0.f;
        #pragma unroll 4
        for (int c = 0; c < CDIM; c += 4) {
            float4 a  = *reinterpret_cast<const float4*>(&sx[i][c]);
            float4 bb = *reinterpret_cast<const float4*>(&sx[j][c]);
            acc += a.x * bb.x + a.y * bb.y + a.z * bb.z + a.w * bb.w;
        }
        ssim[i][j] = acc;
        ssim[j][i] = acc;
    }
    __syncthreads();

    if (tid < NNODE) {
        float v[NNODE];
        #pragma unroll
        for (int j = 0; j < NNODE; j++) v[j] = ssim[tid][j];
        float thr = 0.f;
        #pragma unroll
        for (int t = 0; t < TOPK; t++) {
            int m = 0;
            float mv = v[0];
            #pragma unroll
            for (int j = 1; j < NNODE; j++) if (v[j] > mv) { mv = v[j]; m = j; }
            thr = mv;
            v[m] = -3.4e38f;
        }
        sthr[tid] = thr;
        int deg = 0;
        #pragma unroll
        for (int j = 0; j < NNODE; j++) deg += (ssim[tid][j] >= thr) ? 1 : 0;
        sdinv[tid] = rsqrtf((float)deg);
    }
    __syncthreads();

    for (int t = tid; t < NNODE * NNODE; t += 128) {   // 144 > 128: grid-stride
        int i = t / NNODE, j = t % NNODE;
        float adj = (ssim[i][j] >= sthr[i]) ? 1.f : 0.f;
        sA[i][j] = sdinv[i] * sdinv[j] * adj;
    }
    __syncthreads();

    if (tid < NNODE) {
        float rs = 0.f;
        #pragma unroll
        for (int j = 0; j < NNODE; j++) rs += sA[tid][j];
        g_rs[(size_t)b * NNODE + tid] = rs;
    }

    // y = A @ x -> cols [0,512).  4 consecutive channels per thread: sA loads
    // amortized 4x, stores vectorized.
    {
        const int c0 = tid * 4;
        float4 xv[NNODE];
        #pragma unroll
        for (int j = 0; j < NNODE; j++)
            xv[j] = *reinterpret_cast<const float4*>(&sx[j][c0]);
        #pragma unroll
        for (int i = 0; i < NNODE; i++) {
            float a0 = 0.f, a1 = 0.f, a2 = 0.f, a3 = 0.f;
            #pragma unroll
            for (int j = 0; j < NNODE; j++) {
                float w = sA[i][j];
                a0 += w * xv[j].x; a1 += w * xv[j].y;
                a2 += w * xv[j].z; a3 += w * xv[j].w;
            }
            size_t o = ((size_t)b * NNODE + i) * KDIM + c0;
            uint2 hi = make_uint2(pack_hi2(a0, a1), pack_hi2(a2, a3));
            uint2 lo = make_uint2(pack_lo2(a0, a1), pack_lo2(a2, a3));
            *reinterpret_cast<uint2*>(g_ahi + o) = hi;
            *reinterpret_cast<uint2*>(g_alo + o) = lo;
        }
    }

    // x -> cols [512,1024), vectorized
    for (int u = tid; u < NNODE * 128; u += 128) {
        int i = u >> 7, q = u & 127;
        float4 v = *reinterpret_cast<const float4*>(&sx[i][q * 4]);
        size_t o = ((size_t)b * NNODE + i) * KDIM + 512 + q * 4;
        uint2 hi = make_uint2(pack_hi2(v.x, v.y), pack_hi2(v.z, v.w));
        uint2 lo = make_uint2(pack_lo2(v.x, v.y), pack_lo2(v.z, v.w));
        *reinterpret_cast<uint2*>(g_ahi + o) = hi;
        *reinterpret_cast<uint2*>(g_alo + o) = lo;
    }
}

// ============================================================================
// Kernel 2: GEMM  h = [y|x] @ Wcat^T + rs*Vb + Ub   (bf16x3, HMMA, ldmatrix)
// BM=128, BN=128, BK=32, 256 threads, 2-stage cp.async, 2 CTAs/SM.
// Fused per-node BN stat accumulation in the epilogue.
// ============================================================================
#define LDA        40
#define TILE_B     (128 * LDA)
#define STAGE_E    (4 * TILE_B)
#define STAGE_BYTES (STAGE_E * 2)          // 40960
#define SMEM2_BYTES (2 * STAGE_BYTES)      // 81920

__device__ __forceinline__ void issue_chunk(uint32_t sbase, int mrow0, int n0,
                                            int kc, int arow, int acol) {
    const size_t ga = (size_t)(mrow0 + arow) * KDIM + kc * 32 + acol;
    const size_t gw = (size_t)(n0 + arow) * KDIM + kc * 32 + acol;
    const uint32_t off = (uint32_t)(arow * LDA + acol) * 2;
    cp_async16(sbase + off,                     g_ahi + ga);
    cp_async16(sbase + off + 16,                g_ahi + ga + 8);
    cp_async16(sbase + TILE_B * 2 + off,        g_alo + ga);
    cp_async16(sbase + TILE_B * 2 + off + 16,   g_alo + ga + 8);
    cp_async16(sbase + 2 * TILE_B * 2 + off,      g_whi + gw);
    cp_async16(sbase + 2 * TILE_B * 2 + off + 16, g_whi + gw + 8);
    cp_async16(sbase + 3 * TILE_B * 2 + off,      g_wlo + gw);
    cp_async16(sbase + 3 * TILE_B * 2 + off + 16, g_wlo + gw + 8);
}

__global__ __launch_bounds__(256, 2) void k_gemm(const float* __restrict__ Vb,
                                                 const float* __restrict__ Ub) {
    extern __shared__ __align__(128) __nv_bfloat16 sm[];
    __shared__ float sBias[256];
    __shared__ float sred[24];

    const int tid  = threadIdx.x;
    const int wid  = tid >> 5;
    const int lane = tid & 31;

    const int ntile = blockIdx.x & 3;
    const int mtile = blockIdx.x >> 2;
    const int mrow0 = mtile * 128;
    const int n0    = ntile * 128;

    const int wm = (wid & 3) * 32;
    const int wn = (wid >> 2) * 64;

    for (int i = tid; i < 128; i += 256) {
        sBias[i]       = Vb[n0 + i];
        sBias[128 + i] = Ub[n0 + i];
    }
    if (tid < 24) sred[tid] = 0.f;

    float acc[2][8][4];
    #pragma unroll
    for (int mi = 0; mi < 2; mi++)
        #pragma unroll
        for (int nb = 0; nb < 8; nb++)
            #pragma unroll
            for (int q = 0; q < 4; q++) acc[mi][nb][q] = 0.f;

    const int arow = tid >> 1;
    const int acol = (tid & 1) * 16;
    const uint32_t sm_addr = smem_u32(sm);

    issue_chunk(sm_addr, mrow0, n0, 0, arow, acol);
    CP_COMMIT();
    issue_chunk(sm_addr + STAGE_BYTES, mrow0, n0, 1, arow, acol);
    CP_COMMIT();

    #pragma unroll 1
    for (int kc = 0; kc < 32; kc++) {
        CP_WAIT1();
        __syncthreads();

        {
            const uint32_t sA_hi = sm_addr + (uint32_t)(kc & 1) * STAGE_BYTES;
            const uint32_t sA_lo = sA_hi + TILE_B * 2;
            const uint32_t sB_hi = sA_hi + 2 * TILE_B * 2;
            const uint32_t sB_lo = sA_hi + 3 * TILE_B * 2;

            #pragma unroll
            for (int ks = 0; ks < 2; ks++) {
                const int k0 = ks * 16;
                uint32_t aH[2][4], aL[2][4];
                const int afr = lane & 15;
                const int afc = k0 + (lane >> 4) * 8;
                #pragma unroll
                for (int mi = 0; mi < 2; mi++) {
                    uint32_t ad = (uint32_t)((wm + mi * 16 + afr) * LDA + afc) * 2;
                    ldsm_x4(aH[mi], sA_hi + ad);
                    ldsm_x4(aL[mi], sA_lo + ad);
                }
                #pragma unroll
                for (int g = 0; g < 2; g++) {
                    uint32_t bH[4][2], bL[4][2];
                    #pragma unroll
                    for (int nq = 0; nq < 4; nq++) {
                        const int nb = g * 4 + nq;
                        const int brow = wn + nb * 8 + (lane & 7);
                        const int bcol = k0 + ((lane >> 3) & 1) * 8;
                        uint32_t bd = (uint32_t)(brow * LDA + bcol) * 2;
                        ldsm_x2(bH[nq], sB_hi + bd);
                        ldsm_x2(bL[nq], sB_lo + bd);
                    }
                    // term-major: same-acc MMAs are 8 issues apart (no RAW chain)
                    #pragma unroll
                    for (int nq = 0; nq < 4; nq++)
                        #pragma unroll
                        for (int mi = 0; mi < 2; mi++)
                            mma_bf16(acc[mi][g * 4 + nq], aH[mi], bH[nq]);
                    #pragma unroll
                    for (int nq = 0; nq < 4; nq++)
                        #pragma unroll
                        for (int mi = 0; mi < 2; mi++)
                            mma_bf16(acc[mi][g * 4 + nq], aL[mi], bH[nq]);
                    #pragma unroll
                    for (int nq = 0; nq < 4; nq++)
                        #pragma unroll
                        for (int mi = 0; mi < 2; mi++)
                            mma_bf16(acc[mi][g * 4 + nq], aH[mi], bL[nq]);
                }
            }
        }
        __syncthreads();

        const int kn = kc + 2;
        if (kn < 32)
            issue_chunk(sm_addr + (uint32_t)(kc & 1) * STAGE_BYTES, mrow0, n0, kn, arow, acol);
        CP_COMMIT();
    }

    // ---- epilogue: bias + write h + fused BN stats ----
    const int l4 = lane >> 2;
    const int lc = (lane & 3) * 2;

    #pragma unroll
    for (int mi = 0; mi < 2; mi++) {
        #pragma unroll
        for (int rr = 0; rr < 2; rr++) {
            const int row = wm + mi * 16 + rr * 8 + l4;
            const size_t grow = (size_t)mrow0 + row;
            const float rsv = g_rs[grow];
            float* hrow = g_h + grow * CDIM + n0;
            float lsum = 0.f, lsq = 0.f;
            #pragma unroll
            for (int nb = 0; nb < 8; nb++) {
                const int c = wn + nb * 8 + lc;
                float v0 = acc[mi][nb][rr * 2 + 0] + rsv * sBias[c]     + sBias[128 + c];
                float v1 = acc[mi][nb][rr * 2 + 1] + rsv * sBias[c + 1] + sBias[128 + c + 1];
                lsum += v0 + v1;
                lsq  += v0 * v0 + v1 * v1;
                *reinterpret_cast<float2*>(hrow + c) = make_float2(v0, v1);
            }
            lsum += __shfl_xor_sync(0xFFFFFFFF, lsum, 1);
            lsq  += __shfl_xor_sync(0xFFFFFFFF, lsq, 1);
            lsum += __shfl_xor_sync(0xFFFFFFFF, lsum, 2);
            lsq  += __shfl_xor_sync(0xFFFFFFFF, lsq, 2);
            if ((lane & 3) == 0) {
                int node = (int)(grow % NNODE);
                atomicAdd(&sred[node], lsum);
                atomicAdd(&sred[12 + node], lsq);
            }
        }
    }
    __syncthreads();
    if (tid < NNODE) {
        atomicAdd(&g_sum[tid], sred[tid]);
        atomicAdd(&g_sumsq[tid], sred[12 + tid]);
    }
}

// ============================================================================
// Kernel 3: finalize BN stats -> scale/shift per node
// ============================================================================
__global__ void k_finalize(const float* __restrict__ gamma, const float* __restrict__ beta) {
    int t = threadIdx.x;
    if (t < NNODE) {
        const float inv_n = 1.0f / ((float)NB * (float)CDIM);
        float mean = g_sum[t] * inv_n;
        float var  = g_sumsq[t] * inv_n - mean * mean;
        var = fmaxf(var, 0.f);
        float sc = gamma[t] * rsqrtf(var + BN_EPS);
        g_scale[t] = sc;
        g_shift[t] = beta[t] - mean * sc;
    }
}

// ============================================================================
// Kernel 4: out = relu(x + h*scale + shift)
// ============================================================================
__global__ __launch_bounds__(512) void k_output(const float* __restrict__ x,
                                                float* __restrict__ out) {
    size_t idx = (size_t)blockIdx.x * 512 + threadIdx.x;
    const float4 xv = reinterpret_cast<const float4*>(x)[idx];
    const float4 hv = reinterpret_cast<const float4*>(g_h)[idx];
    int node = (int)((idx >> 7) % NNODE);
    float sc = g_scale[node], sh = g_shift[node];
    float4 o;
    o.x = fmaxf(fmaf(hv.x, sc, sh) + xv.x, 0.f);
    o.y = fmaxf(fmaf(hv.y, sc, sh) + xv.y, 0.f);
    o.z = fmaxf(fmaf(hv.z, sc, sh) + xv.z, 0.f);
    o.w = fmaxf(fmaf(hv.w, sc, sh) + xv.w, 0.f);
    reinterpret_cast<float4*>(out)[idx] = o;
}

// ============================================================================
// Launch
// ============================================================================
extern "C" void kernel_launch(void* const* d_in, const int* in_sizes, int n_in,
                              void* d_out, int out_size) {
    const float* x     = (const float*)d_in[0];
    const float* Uw    = (const float*)d_in[1];
    const float* Ub    = (const float*)d_in[2];
    const float* Vw    = (const float*)d_in[3];
    const float* Vb    = (const float*)d_in[4];
    const float* gamma = (const float*)d_in[5];
    const float* beta  = (const float*)d_in[6];
    float* out = (float*)d_out;

    cudaFuncSetAttribute(k_gemm, cudaFuncAttributeMaxDynamicSharedMemorySize, SMEM2_BYTES);

    k_zero_stats<<<1, 32>>>();
    k_prep_w<<<(NDIM * KDIM + 255) / 256, 256>>>(Uw, Vw);
    k_adjacency<<<NB, 128>>>(x);
    k_gemm<<<(ROWS / 128) * 4, 256, SMEM2_BYTES>>>(Vb, Ub);
    k_finalize<<<1, 32>>>(gamma, beta);
    k_output<<<(unsigned)((size_t)ROWS * CDIM / 4 / 512), 512>>>(x, out);
}